// round 14
// baseline (speedup 1.0000x reference)
#include <cuda_runtime.h>
#include <cuda_bf16.h>
#include <math.h>
#include <stdint.h>

// ---------------- problem constants ----------------
#define TK   4096      // tokens = B*S
#define HH   1024      // hidden
#define SS   2048      // seq len
#define NHH  16        // heads
#define BHN  32        // B*NH
#define II   384       // expert intermediate
#define NE   8         // routed experts

// ---------------- scratch ----------------
__device__ float g_xi [TK*HH];
__device__ float g_cq [TK*128];
__device__ float g_ckv[TK*128];
__device__ float g_qn [TK*512];
__device__ float g_qr [TK*512];
__device__ float g_kn [TK*512];
__device__ float g_kr [TK*512];
__device__ float g_vx [TK*HH];
__device__ float g_q  [TK*HH];   // [bh][s][64]
__device__ float g_k  [TK*HH];
__device__ float g_o  [TK*HH];
__device__ float g_h  [TK*HH];
__device__ float g_hn [TK*HH];
__device__ float g_gt [(NE+2)*TK*II];
__device__ float g_ut [(NE+2)*TK*II];
__device__ int   g_cnt[NE];
__device__ int   g_tok[NE*TK];
__device__ float g_twt[NE*TK];

// ---------------- mma helpers ----------------
__device__ __forceinline__ void mma16(float* c, const uint32_t* a, const uint32_t* b) {
    asm volatile(
        "mma.sync.aligned.m16n8k16.row.col.f32.bf16.bf16.f32 "
        "{%0,%1,%2,%3}, {%4,%5,%6,%7}, {%8,%9}, {%0,%1,%2,%3};\n"
        : "+f"(c[0]), "+f"(c[1]), "+f"(c[2]), "+f"(c[3])
        : "r"(a[0]), "r"(a[1]), "r"(a[2]), "r"(a[3]), "r"(b[0]), "r"(b[1]));
}
__device__ __forceinline__ uint32_t pkbf2(float a, float b) {
    __nv_bfloat162 t = __floats2bfloat162_rn(a, b);
    return *reinterpret_cast<uint32_t*>(&t);
}
__device__ __forceinline__ float siluf(float v) {
    return v / (1.f + __expf(-v));
}

// ---------------- unified bf16 GEMM ----------------
#define GASTR 20
#define GBSTR 136
#define GASZ  (128*GASTR)
#define GBSZ  (16*GBSTR)

struct GArgs {
    const float* A; int lda; size_t aes;
    const float* A2;                      // if set: A-elem = silu(A)*A2 (same layout)
    const float* B[3]; int ldb[3]; size_t bes[3];
    float*       C[3]; int ldc[3]; size_t ces[3];
    int n1, n2;
    int M, N, K;
    const int* tok; int gatherA; int scatterC;
    const float* wt; const float* addsrc; int accAtomic;
    const int* cnt; int splitK;
};

__global__ void __launch_bounds__(256) gemm_bfx(GArgs ga)
{
    extern __shared__ uint32_t sm[];
    uint32_t* As = sm;
    uint32_t* Bs = sm + 2 * GASZ;
    __shared__ int idxs[128];

    int e, kbase, Ke;
    if (ga.splitK > 1) { e = 0; Ke = ga.K / ga.splitK; kbase = blockIdx.z * Ke; }
    else               { e = blockIdx.z; Ke = ga.K; kbase = 0; }

    const int m0 = blockIdx.y * 128;
    const int n0 = blockIdx.x * 128;

    int seg = 0, nloc = n0;
    if (ga.B[1] && n0 >= ga.n1) {
        if (ga.B[2] && n0 >= ga.n1 + ga.n2) { seg = 2; nloc = n0 - ga.n1 - ga.n2; }
        else                                { seg = 1; nloc = n0 - ga.n1; }
    }
    const float* A  = ga.A + (size_t)e * ga.aes;
    const float* A2 = ga.A2 ? ga.A2 + (size_t)e * ga.aes : nullptr;
    const float* B = ga.B[seg] + (size_t)e * ga.bes[seg];
    float*       C = ga.C[seg] + (size_t)e * ga.ces[seg];
    const int lda = ga.lda, ldb = ga.ldb[seg], ldc = ga.ldc[seg];
    const int* idx = ga.tok ? ga.tok + (size_t)e * TK : nullptr;
    const float* wt = ga.wt ? ga.wt + (size_t)e * TK : nullptr;
    const int effM = ga.cnt ? ga.cnt[e] : ga.M;
    if (m0 >= effM) return;

    const int tid = threadIdx.x;
    if (idx) {
        for (int i = tid; i < 128; i += 256) {
            int m = m0 + i;
            idxs[i] = (m < effM) ? idx[m] : 0;
        }
        __syncthreads();
    }

    const int am = tid >> 4, ak2 = tid & 15;
    const int bn = tid & 127, bk2 = tid >> 7;

    float2 areg[8];
    float  breg[16];

    auto ldgTile = [&](int kt) {
        #pragma unroll
        for (int i = 0; i < 8; i++) {
            int m = am + i * 16;
            int mg = m0 + m;
            float2 v = make_float2(0.f, 0.f);
            if (mg < effM) {
                int row = ga.gatherA ? idxs[m] : mg;
                size_t off = (size_t)row * lda + kt + 2 * ak2;
                v = *(const float2*)(A + off);
                if (A2) {
                    float2 v2 = *(const float2*)(A2 + off);
                    v.x = siluf(v.x) * v2.x;
                    v.y = siluf(v.y) * v2.y;
                }
            }
            areg[i] = v;
        }
        #pragma unroll
        for (int i = 0; i < 8; i++) {
            int kk = kt + 2 * (bk2 + i * 2);
            breg[2 * i]     = B[(size_t)kk * ldb + nloc + bn];
            breg[2 * i + 1] = B[(size_t)(kk + 1) * ldb + nloc + bn];
        }
    };
    auto stsTile = [&](int buf) {
        uint32_t* Ad = As + buf * GASZ;
        #pragma unroll
        for (int i = 0; i < 8; i++)
            Ad[(am + i * 16) * GASTR + ak2] = pkbf2(areg[i].x, areg[i].y);
        uint32_t* Bd = Bs + buf * GBSZ;
        #pragma unroll
        for (int i = 0; i < 8; i++)
            Bd[(bk2 + i * 2) * GBSTR + bn] = pkbf2(breg[2 * i], breg[2 * i + 1]);
    };

    const int lane = tid & 31, wid = tid >> 5;
    const int wm = (wid >> 2) * 64;
    const int wn = (wid & 3) * 32;
    const int g = lane >> 2, c = lane & 3;

    float acc[4][4][4];
    #pragma unroll
    for (int i = 0; i < 4; i++)
        #pragma unroll
        for (int j = 0; j < 4; j++)
            #pragma unroll
            for (int r = 0; r < 4; r++) acc[i][j][r] = 0.f;

    ldgTile(kbase);
    stsTile(0);
    __syncthreads();

    const int nbuf = Ke >> 5;
    for (int t = 0; t < nbuf; t++) {
        int cur = t & 1;
        if (t + 1 < nbuf) ldgTile(kbase + ((t + 1) << 5));

        const uint32_t* Ab = As + cur * GASZ;
        const uint32_t* Bb = Bs + cur * GBSZ;
        #pragma unroll
        for (int kp = 0; kp < 16; kp += 8) {
            uint32_t af[4][4];
            #pragma unroll
            for (int mt = 0; mt < 4; mt++) {
                int mb = wm + mt * 16;
                af[mt][0] = Ab[(mb + g) * GASTR + kp + c];
                af[mt][1] = Ab[(mb + g + 8) * GASTR + kp + c];
                af[mt][2] = Ab[(mb + g) * GASTR + kp + c + 4];
                af[mt][3] = Ab[(mb + g + 8) * GASTR + kp + c + 4];
            }
            uint32_t bf[4][2];
            #pragma unroll
            for (int nt = 0; nt < 4; nt++) {
                int nb = wn + nt * 8;
                bf[nt][0] = Bb[(kp + c) * GBSTR + nb + g];
                bf[nt][1] = Bb[(kp + c + 4) * GBSTR + nb + g];
            }
            #pragma unroll
            for (int mt = 0; mt < 4; mt++)
                #pragma unroll
                for (int nt = 0; nt < 4; nt++)
                    mma16(acc[mt][nt], af[mt], bf[nt]);
        }
        if (t + 1 < nbuf) stsTile(cur ^ 1);
        __syncthreads();
    }

    #pragma unroll
    for (int mt = 0; mt < 4; mt++) {
        #pragma unroll
        for (int h2 = 0; h2 < 2; h2++) {
            int ml = wm + mt * 16 + g + h2 * 8;
            int m = m0 + ml;
            if (m >= effM) continue;
            int crow = ga.scatterC ? idxs[ml] : m;
            float sc = wt ? wt[m] : 1.f;
            #pragma unroll
            for (int nt = 0; nt < 4; nt++) {
                int ncol = nloc + wn + nt * 8 + c * 2;
                float v0 = acc[mt][nt][h2 * 2 + 0];
                float v1 = acc[mt][nt][h2 * 2 + 1];
                float* cp = C + (size_t)crow * ldc + ncol;
                if (ga.splitK > 1) {
                    atomicAdd(cp, v0); atomicAdd(cp + 1, v1);
                } else if (wt) {
                    atomicAdd(cp, sc * v0); atomicAdd(cp + 1, sc * v1);
                } else if (ga.accAtomic) {
                    atomicAdd(cp, v0); atomicAdd(cp + 1, v1);
                } else if (ga.addsrc) {
                    const float* ap = ga.addsrc + (size_t)m * ldc + ncol;
                    cp[0] = v0 + ap[0]; cp[1] = v1 + ap[1];
                } else {
                    cp[0] = v0; cp[1] = v1;
                }
            }
        }
    }
}

// ---------------- RMSNorm ----------------
__global__ void rms_k(const float* __restrict__ x, const float* __restrict__ w,
                      float* __restrict__ y, int D)
{
    int t = blockIdx.x;
    const float* xr = x + (size_t)t * D;
    float* yr = y + (size_t)t * D;
    float ss = 0.f;
    for (int k = threadIdx.x; k < D; k += blockDim.x) { float v = xr[k]; ss += v * v; }
    __shared__ float sh[32];
    int lane = threadIdx.x & 31, wid = threadIdx.x >> 5;
    #pragma unroll
    for (int o = 16; o > 0; o >>= 1) ss += __shfl_xor_sync(0xffffffffu, ss, o);
    if (lane == 0) sh[wid] = ss;
    __syncthreads();
    if (threadIdx.x == 0) {
        float tot = 0.f;
        int nw = blockDim.x >> 5;
        for (int i = 0; i < nw; i++) tot += sh[i];
        sh[0] = tot;
    }
    __syncthreads();
    float r = rsqrtf(sh[0] / (float)D + 1e-5f);
    for (int k = threadIdx.x; k < D; k += blockDim.x) yr[k] = w[k] * xr[k] * r;
}

// ---------------- fused: hn = rms(h), out = h, router top-2 ----------------
__global__ void __launch_bounds__(256) rms2_router_k(
    const float* __restrict__ h, const float* __restrict__ ln2w,
    const float* __restrict__ rw, const float* __restrict__ rb,
    float* __restrict__ hn, float* __restrict__ outp,
    int* __restrict__ cnt, int* __restrict__ tok, float* __restrict__ twt)
{
    int t = blockIdx.x;
    const int tid = threadIdx.x;
    const float* hr = h + (size_t)t * HH;
    float* hnr = hn + (size_t)t * HH;
    float* outr = outp + (size_t)t * HH;

    float hv[4];
    float ss = 0.f;
    #pragma unroll
    for (int i = 0; i < 4; i++) {
        int k = tid + i * 256;
        float v = hr[k];
        hv[i] = v;
        outr[k] = v;            // out = h (residual copy)
        ss += v * v;
    }
    __shared__ float sh[32];
    int lane = tid & 31, wid = tid >> 5;
    #pragma unroll
    for (int o = 16; o > 0; o >>= 1) ss += __shfl_xor_sync(0xffffffffu, ss, o);
    if (lane == 0) sh[wid] = ss;
    __syncthreads();
    if (tid == 0) {
        float tot = 0.f;
        for (int i = 0; i < 8; i++) tot += sh[i];
        sh[0] = tot;
    }
    __syncthreads();
    float r = rsqrtf(sh[0] / (float)HH + 1e-5f);

    float accv[NE];
    #pragma unroll
    for (int e = 0; e < NE; e++) accv[e] = 0.f;
    #pragma unroll
    for (int i = 0; i < 4; i++) {
        int k = tid + i * 256;
        float nv = ln2w[k] * hv[i] * r;
        hnr[k] = nv;
        const float* wrow = rw + (size_t)k * NE;
        #pragma unroll
        for (int e = 0; e < NE; e++) accv[e] += nv * wrow[e];
    }
    // block-reduce 8 logits
    __shared__ float red[256][NE];
    #pragma unroll
    for (int e = 0; e < NE; e++) red[tid][e] = accv[e];
    __syncthreads();
    for (int s = 128; s > 0; s >>= 1) {
        if (tid < s)
            #pragma unroll
            for (int e = 0; e < NE; e++) red[tid][e] += red[tid + s][e];
        __syncthreads();
    }
    if (tid == 0) {
        float p[NE];
        #pragma unroll
        for (int e = 0; e < NE; e++) {
            float lg = red[0][e] + rb[e];
            p[e] = 1.f / (1.f + expf(-lg));
        }
        int e1 = 0;
        for (int e = 1; e < NE; e++) if (p[e] > p[e1]) e1 = e;
        int e2 = -1;
        for (int e = 0; e < NE; e++) if (e != e1 && (e2 < 0 || p[e] > p[e2])) e2 = e;
        float s2 = p[e1] + p[e2];
        float w1 = p[e1] / s2, w2 = p[e2] / s2;
        int a = atomicAdd(&cnt[e1], 1); tok[e1 * TK + a] = t; twt[e1 * TK + a] = w1;
        int b = atomicAdd(&cnt[e2], 1); tok[e2 * TK + b] = t; twt[e2 * TK + b] = w2;
    }
}

// ---------------- assemble Q/K with RoPE ----------------
__global__ void assemble_k(const float* __restrict__ qn, const float* __restrict__ qr,
                           const float* __restrict__ kn, const float* __restrict__ kr,
                           const float* __restrict__ cosp, const float* __restrict__ sinp,
                           float* __restrict__ Q, float* __restrict__ K)
{
    int idx = blockIdx.x * blockDim.x + threadIdx.x;
    if (idx >= BHN * SS * 64) return;
    int d  = idx & 63;
    int s  = (idx >> 6) & (SS - 1);
    int bh = idx >> 17;
    int b  = bh >> 4, h = bh & 15;
    int t  = b * SS + s;
    float qv, kv;
    if (d < 32) {
        qv = qn[(size_t)t * 512 + h * 32 + d];
        kv = kn[(size_t)t * 512 + h * 32 + d];
    } else {
        int j = d - 32;
        float cc = cosp[s * 32 + j];
        float sn = sinp[s * 32 + j];
        float q1 = qr[(size_t)t * 512 + h * 32 + j];
        float q2 = (j < 16) ? -qr[(size_t)t * 512 + h * 32 + j + 16]
                            :  qr[(size_t)t * 512 + h * 32 + j - 16];
        qv = q1 * cc + q2 * sn;
        float k1 = kr[(size_t)t * 512 + h * 32 + j];
        float k2 = (j < 16) ? -kr[(size_t)t * 512 + h * 32 + j + 16]
                            :  kr[(size_t)t * 512 + h * 32 + j - 16];
        kv = k1 * cc + k2 * sn;
    }
    Q[idx] = qv;
    K[idx] = kv;
}

// ---------------- flash attention, bf16, BM=128 ----------------
#define FQS 36
#define FKS 72
__global__ void __launch_bounds__(256) flash_bf(
    const float* __restrict__ Q, const float* __restrict__ Kg,
    const float* __restrict__ Vx, const float* __restrict__ maskp,
    float* __restrict__ O)
{
    extern __shared__ uint32_t sm[];
    uint32_t* Qs = sm;
    uint32_t* Kt = sm + 128 * FQS;
    uint32_t* Ps = Kt + 32 * FKS;
    uint32_t* Vs = Ps + 128 * FQS;

    const int bh = blockIdx.y;
    const int q0 = blockIdx.x * 128;
    const int b  = bh >> 4, hh = bh & 15;
    const float* Qb = Q  + (size_t)bh * SS * 64;
    const float* Kb = Kg + (size_t)bh * SS * 64;
    const float* Vb = Vx + (size_t)b * SS * HH + hh * 64;

    const int tid = threadIdx.x;
    const int w = tid >> 5, lane = tid & 31;
    const int g = lane >> 2, c = lane & 3;
    const int wrow = w * 16;

    const int qlr  = tid & 127;
    const int qlc0 = (tid >> 7) * 32;
    const int klr  = tid & 63;
    const int klc0 = (tid >> 6) * 16;
    const int vkp  = tid & 31;
    const int vdb  = (tid >> 5) * 8;

    {
        const float4* src = (const float4*)(Qb + (size_t)(q0 + qlr) * 64 + qlc0);
        #pragma unroll
        for (int i = 0; i < 8; i++) {
            float4 v = src[i];
            uint32_t* d = Qs + qlr * FQS + (qlc0 >> 1) + i * 2;
            d[0] = pkbf2(v.x, v.y);
            d[1] = pkbf2(v.z, v.w);
        }
    }

    float4 kreg[4];
    float4 vreg0[2], vreg1[2];
    auto ldgKV = [&](int k0) {
        const float4* ks = (const float4*)(Kb + (size_t)(k0 + klr) * 64 + klc0);
        #pragma unroll
        for (int i = 0; i < 4; i++) kreg[i] = ks[i];
        const float* v0p = Vb + (size_t)(k0 + 2 * vkp) * HH + vdb;
        const float* v1p = v0p + HH;
        #pragma unroll
        for (int i = 0; i < 2; i++) {
            vreg0[i] = *(const float4*)(v0p + i * 4);
            vreg1[i] = *(const float4*)(v1p + i * 4);
        }
    };
    auto stsKV = [&]() {
        #pragma unroll
        for (int i = 0; i < 4; i++) {
            float4 kv = kreg[i];
            int dp = (klc0 + i * 4) >> 1;
            Kt[(dp + 0) * FKS + klr] = pkbf2(kv.x, kv.y);
            Kt[(dp + 1) * FKS + klr] = pkbf2(kv.z, kv.w);
        }
        #pragma unroll
        for (int i = 0; i < 2; i++) {
            float4 a = vreg0[i];
            float4 bb = vreg1[i];
            uint32_t* vd = Vs + vkp * FKS + vdb + i * 4;
            vd[0] = pkbf2(a.x, bb.x);
            vd[1] = pkbf2(a.y, bb.y);
            vd[2] = pkbf2(a.z, bb.z);
            vd[3] = pkbf2(a.w, bb.w);
        }
    };

    float oacc[8][4];
    #pragma unroll
    for (int nf = 0; nf < 8; nf++)
        #pragma unroll
        for (int r = 0; r < 4; r++) oacc[nf][r] = 0.f;
    float m0 = -1e30f, m1 = -1e30f, l0 = 0.f, l1 = 0.f;

    const float* mr0 = maskp + (size_t)(q0 + wrow + g) * SS;
    const float* mr1 = mr0 + 8 * SS;

    ldgKV(0);
    for (int k0 = 0; k0 < SS; k0 += 64) {
        __syncthreads();
        stsKV();
        __syncthreads();
        if (k0 + 64 < SS) ldgKV(k0 + 64);

        float sacc[8][4];
        #pragma unroll
        for (int nf = 0; nf < 8; nf++)
            #pragma unroll
            for (int r = 0; r < 4; r++) sacc[nf][r] = 0.f;
        #pragma unroll
        for (int ks = 0; ks < 32; ks += 8) {
            uint32_t af[4];
            af[0] = Qs[(wrow + g) * FQS + ks + c];
            af[1] = Qs[(wrow + g + 8) * FQS + ks + c];
            af[2] = Qs[(wrow + g) * FQS + ks + c + 4];
            af[3] = Qs[(wrow + g + 8) * FQS + ks + c + 4];
            #pragma unroll
            for (int nf = 0; nf < 8; nf++) {
                uint32_t bf[2];
                bf[0] = Kt[(ks + c) * FKS + nf * 8 + g];
                bf[1] = Kt[(ks + c + 4) * FKS + nf * 8 + g];
                mma16(sacc[nf], af, bf);
            }
        }

        float mx0 = -1e30f, mx1 = -1e30f;
        #pragma unroll
        for (int nf = 0; nf < 8; nf++) {
            float2 mk0 = *(const float2*)(mr0 + k0 + nf * 8 + 2 * c);
            float2 mk1 = *(const float2*)(mr1 + k0 + nf * 8 + 2 * c);
            sacc[nf][0] = sacc[nf][0] * 0.125f + mk0.x;
            sacc[nf][1] = sacc[nf][1] * 0.125f + mk0.y;
            sacc[nf][2] = sacc[nf][2] * 0.125f + mk1.x;
            sacc[nf][3] = sacc[nf][3] * 0.125f + mk1.y;
            mx0 = fmaxf(mx0, fmaxf(sacc[nf][0], sacc[nf][1]));
            mx1 = fmaxf(mx1, fmaxf(sacc[nf][2], sacc[nf][3]));
        }
        mx0 = fmaxf(mx0, __shfl_xor_sync(0xffffffffu, mx0, 1));
        mx0 = fmaxf(mx0, __shfl_xor_sync(0xffffffffu, mx0, 2));
        mx1 = fmaxf(mx1, __shfl_xor_sync(0xffffffffu, mx1, 1));
        mx1 = fmaxf(mx1, __shfl_xor_sync(0xffffffffu, mx1, 2));

        float mn0 = fmaxf(m0, mx0), mn1 = fmaxf(m1, mx1);
        float cr0 = __expf(m0 - mn0), cr1 = __expf(m1 - mn1);
        m0 = mn0; m1 = mn1;
        float rs0 = 0.f, rs1 = 0.f;
        #pragma unroll
        for (int nf = 0; nf < 8; nf++) {
            sacc[nf][0] = __expf(sacc[nf][0] - mn0);
            sacc[nf][1] = __expf(sacc[nf][1] - mn0);
            sacc[nf][2] = __expf(sacc[nf][2] - mn1);
            sacc[nf][3] = __expf(sacc[nf][3] - mn1);
            rs0 += sacc[nf][0] + sacc[nf][1];
            rs1 += sacc[nf][2] + sacc[nf][3];
        }
        rs0 += __shfl_xor_sync(0xffffffffu, rs0, 1);
        rs0 += __shfl_xor_sync(0xffffffffu, rs0, 2);
        rs1 += __shfl_xor_sync(0xffffffffu, rs1, 1);
        rs1 += __shfl_xor_sync(0xffffffffu, rs1, 2);
        l0 = l0 * cr0 + rs0;
        l1 = l1 * cr1 + rs1;
        #pragma unroll
        for (int nf = 0; nf < 8; nf++) {
            oacc[nf][0] *= cr0; oacc[nf][1] *= cr0;
            oacc[nf][2] *= cr1; oacc[nf][3] *= cr1;
        }

        #pragma unroll
        for (int nf = 0; nf < 8; nf++) {
            int kp = nf * 4 + c;
            Ps[(wrow + g) * FQS + kp]     = pkbf2(sacc[nf][0], sacc[nf][1]);
            Ps[(wrow + g + 8) * FQS + kp] = pkbf2(sacc[nf][2], sacc[nf][3]);
        }
        __syncwarp();

        #pragma unroll
        for (int kk = 0; kk < 32; kk += 8) {
            uint32_t af[4];
            af[0] = Ps[(wrow + g) * FQS + kk + c];
            af[1] = Ps[(wrow + g + 8) * FQS + kk + c];
            af[2] = Ps[(wrow + g) * FQS + kk + c + 4];
            af[3] = Ps[(wrow + g + 8) * FQS + kk + c + 4];
            #pragma unroll
            for (int nf = 0; nf < 8; nf++) {
                uint32_t bf[2];
                bf[0] = Vs[(kk + c) * FKS + nf * 8 + g];
                bf[1] = Vs[(kk + c + 4) * FKS + nf * 8 + g];
                mma16(oacc[nf], af, bf);
            }
        }
    }

    float inv0 = 1.f / l0, inv1 = 1.f / l1;
    int row0 = q0 + wrow + g;
    float* o0 = O + ((size_t)(b * SS + row0)) * HH + hh * 64;
    float* o1 = o0 + 8 * (size_t)HH;
    #pragma unroll
    for (int nf = 0; nf < 8; nf++) {
        int col = nf * 8 + 2 * c;
        float2 v0 = make_float2(oacc[nf][0] * inv0, oacc[nf][1] * inv0);
        float2 v1 = make_float2(oacc[nf][2] * inv1, oacc[nf][3] * inv1);
        *(float2*)(o0 + col) = v0;
        *(float2*)(o1 + col) = v1;
    }
}

__global__ void usage_k(const int* __restrict__ cnt, float* __restrict__ out)
{
    int e = threadIdx.x;
    if (e < NE) out[e] = (float)cnt[e];
}

// ---------------- host-side dispatch ----------------
static const int SMEMB = (2 * (GASZ + GBSZ)) * 4;   // 37888
static const int SMEMF = (128 * FQS + 32 * FKS + 128 * FQS + 32 * FKS) * 4;  // 55296

static GArgs mkargs(const float* A, int lda, size_t aes,
                    const float* B0, int ldb0, size_t bes0,
                    float* C0, int ldc0, size_t ces0,
                    int M, int N, int K)
{
    GArgs ga = {};
    ga.A = A; ga.lda = lda; ga.aes = aes;
    ga.B[0] = B0; ga.ldb[0] = ldb0; ga.bes[0] = bes0;
    ga.C[0] = C0; ga.ldc[0] = ldc0; ga.ces[0] = ces0;
    ga.n1 = N; ga.n2 = 0;
    ga.M = M; ga.N = N; ga.K = K;
    ga.splitK = 1;
    return ga;
}

static void launch(cudaStream_t st, const GArgs& ga, int nz)
{
    dim3 grid(ga.N / 128, (ga.M + 127) / 128, nz);
    gemm_bfx<<<grid, 256, SMEMB, st>>>(ga);
}

extern "C" void kernel_launch(void* const* d_in, const int* in_sizes, int n_in,
                              void* d_out, int out_size)
{
    const float* x        = (const float*)d_in[0];
    const float* cosp     = (const float*)d_in[1];
    const float* sinp     = (const float*)d_in[2];
    const float* maskp    = (const float*)d_in[3];
    const float* ln1      = (const float*)d_in[4];
    const float* ln2      = (const float*)d_in[5];
    const float* kv_down  = (const float*)d_in[6];
    const float* kv_norm  = (const float*)d_in[7];
    const float* w_uk     = (const float*)d_in[8];
    const float* w_ur     = (const float*)d_in[9];
    const float* w_uv     = (const float*)d_in[10];
    const float* q_down   = (const float*)d_in[11];
    const float* q_norm   = (const float*)d_in[12];
    const float* w_uq     = (const float*)d_in[13];
    const float* w_qr     = (const float*)d_in[14];
    const float* o_proj   = (const float*)d_in[15];
    const float* sh_gate  = (const float*)d_in[16];
    const float* sh_up    = (const float*)d_in[17];
    const float* sh_down  = (const float*)d_in[18];
    const float* r_gate   = (const float*)d_in[19];
    const float* r_up     = (const float*)d_in[20];
    const float* r_down   = (const float*)d_in[21];
    const float* router_w = (const float*)d_in[22];
    const float* router_b = (const float*)d_in[23];
    float* out = (float*)d_out;

    float *xi, *cq, *ckv, *qn, *qr, *kn, *kr, *vx, *q, *k, *o, *h, *hn, *gt, *ut, *twt;
    int *cnt, *tok;
    cudaGetSymbolAddress((void**)&xi,  g_xi);
    cudaGetSymbolAddress((void**)&cq,  g_cq);
    cudaGetSymbolAddress((void**)&ckv, g_ckv);
    cudaGetSymbolAddress((void**)&qn,  g_qn);
    cudaGetSymbolAddress((void**)&qr,  g_qr);
    cudaGetSymbolAddress((void**)&kn,  g_kn);
    cudaGetSymbolAddress((void**)&kr,  g_kr);
    cudaGetSymbolAddress((void**)&vx,  g_vx);
    cudaGetSymbolAddress((void**)&q,   g_q);
    cudaGetSymbolAddress((void**)&k,   g_k);
    cudaGetSymbolAddress((void**)&o,   g_o);
    cudaGetSymbolAddress((void**)&h,   g_h);
    cudaGetSymbolAddress((void**)&hn,  g_hn);
    cudaGetSymbolAddress((void**)&gt,  g_gt);
    cudaGetSymbolAddress((void**)&ut,  g_ut);
    cudaGetSymbolAddress((void**)&twt, g_twt);
    cudaGetSymbolAddress((void**)&cnt, g_cnt);
    cudaGetSymbolAddress((void**)&tok, g_tok);

    cudaFuncSetAttribute(gemm_bfx, cudaFuncAttributeMaxDynamicSharedMemorySize, SMEMB);
    cudaFuncSetAttribute(flash_bf, cudaFuncAttributeMaxDynamicSharedMemorySize, SMEMF);

    cudaStream_t s0 = 0, s1;
    cudaStreamCreateWithFlags(&s1, cudaStreamNonBlocking);
    cudaEvent_t ev0, ev1, ev2, ev3;
    cudaEventCreateWithFlags(&ev0, cudaEventDisableTiming);
    cudaEventCreateWithFlags(&ev1, cudaEventDisableTiming);
    cudaEventCreateWithFlags(&ev2, cudaEventDisableTiming);
    cudaEventCreateWithFlags(&ev3, cudaEventDisableTiming);

    const size_t TI = (size_t)TK * II;
    const size_t WE = (size_t)HH * II;
    const size_t WD = (size_t)II * HH;

    // ---- MLA attention ----
    rms_k<<<TK, 256, 0, s0>>>(x, ln1, xi, HH);

    cudaMemsetAsync(cq, 0, (size_t)TK * 128 * sizeof(float), s0);
    cudaMemsetAsync(ckv, 0, (size_t)TK * 128 * sizeof(float), s0);
    {
        GArgs ga = mkargs(xi, HH, 0, q_down, 128, 0, cq, 128, 0, TK, 256, HH);
        ga.n1 = 128;
        ga.B[1] = kv_down; ga.ldb[1] = 128; ga.bes[1] = 0;
        ga.C[1] = ckv;     ga.ldc[1] = 128; ga.ces[1] = 0;
        ga.splitK = 4;
        launch(s0, ga, 4);
    }
    rms_k<<<TK, 128, 0, s0>>>(cq, q_norm, cq, 128);
    cudaEventRecord(ev0, s0);
    cudaStreamWaitEvent(s1, ev0, 0);
    rms_k<<<TK, 128, 0, s1>>>(ckv, kv_norm, ckv, 128);

    {
        GArgs ga = mkargs(cq, 128, 0, w_uq, 512, 0, qn, 512, 0, TK, 1024, 128);
        ga.n1 = 512;
        ga.B[1] = w_qr; ga.ldb[1] = 512; ga.bes[1] = 0;
        ga.C[1] = qr;   ga.ldc[1] = 512; ga.ces[1] = 0;
        launch(s0, ga, 1);
    }
    {
        GArgs ga = mkargs(ckv, 128, 0, w_uk, 512, 0, kn, 512, 0, TK, 2048, 128);
        ga.n1 = 512; ga.n2 = 512;
        ga.B[1] = w_ur; ga.ldb[1] = 512;  ga.bes[1] = 0;
        ga.C[1] = kr;   ga.ldc[1] = 512;  ga.ces[1] = 0;
        ga.B[2] = w_uv; ga.ldb[2] = 1024; ga.bes[2] = 0;
        ga.C[2] = vx;   ga.ldc[2] = 1024; ga.ces[2] = 0;
        launch(s1, ga, 1);
    }
    cudaEventRecord(ev1, s1);
    cudaStreamWaitEvent(s0, ev1, 0);

    assemble_k<<<(BHN * SS * 64) / 256, 256, 0, s0>>>(qn, qr, kn, kr, cosp, sinp, q, k);
    flash_bf<<<dim3(SS / 128, BHN), 256, SMEMF, s0>>>(q, k, vx, maskp, o);
    {
        GArgs ga = mkargs(o, HH, 0, o_proj, HH, 0, h, HH, 0, TK, HH, HH);
        ga.addsrc = x;
        launch(s0, ga, 1);
    }

    // ---- MoE (bf16, silu fused into down GEMMs) ----
    cudaMemsetAsync(cnt, 0, NE * sizeof(int), s0);
    rms2_router_k<<<TK, 256, 0, s0>>>(h, ln2, router_w, router_b, hn, out, cnt, tok, twt);
    cudaEventRecord(ev2, s0);
    cudaStreamWaitEvent(s1, ev2, 0);

    // shared experts on s0 (z=2): merged gate|up, then down with fused silu
    {
        GArgs ga = mkargs(hn, HH, 0, sh_gate, II, WE, gt, II, TI, TK, 768, HH);
        ga.n1 = II;
        ga.B[1] = sh_up; ga.ldb[1] = II; ga.bes[1] = WE;
        ga.C[1] = ut;    ga.ldc[1] = II; ga.ces[1] = TI;
        launch(s0, ga, 2);
    }
    {
        GArgs ga = mkargs(gt, II, TI, sh_down, HH, WD, out, HH, 0, TK, HH, II);
        ga.A2 = ut;
        ga.accAtomic = 1;
        launch(s0, ga, 2);
    }

    // routed experts on s1 (z=8, gather): merged gate|up, then down (silu fused, scatter+scale)
    float* gt2 = gt + 2 * TI;
    float* ut2 = ut + 2 * TI;
    {
        GArgs ga = mkargs(hn, HH, 0, r_gate, II, WE, gt2, II, TI, TK, 768, HH);
        ga.n1 = II;
        ga.B[1] = r_up; ga.ldb[1] = II; ga.bes[1] = WE;
        ga.C[1] = ut2;  ga.ldc[1] = II; ga.ces[1] = TI;
        ga.tok = tok; ga.gatherA = 1; ga.cnt = cnt;
        launch(s1, ga, NE);
    }
    {
        GArgs ga = mkargs(gt2, II, TI, r_down, HH, WD, out, HH, 0, TK, HH, II);
        ga.A2 = ut2;
        ga.tok = tok; ga.scatterC = 1; ga.wt = twt; ga.cnt = cnt;
        launch(s1, ga, NE);
    }
    cudaEventRecord(ev3, s1);
    cudaStreamWaitEvent(s0, ev3, 0);

    usage_k<<<1, NE, 0, s0>>>(cnt, out + (size_t)TK * HH);
}

// round 15
// speedup vs baseline: 1.2328x; 1.2328x over previous
#include <cuda_runtime.h>
#include <cuda_bf16.h>
#include <math.h>
#include <stdint.h>

// ---------------- problem constants ----------------
#define TK   4096      // tokens = B*S
#define HH   1024      // hidden
#define SS   2048      // seq len
#define NHH  16        // heads
#define BHN  32        // B*NH
#define II   384       // expert intermediate
#define NE   8         // routed experts

// ---------------- scratch ----------------
__device__ float g_xi [TK*HH];
__device__ float g_cq [TK*128];
__device__ float g_ckv[TK*128];
__device__ float g_qn [TK*512];
__device__ float g_qr [TK*512];
__device__ float g_kn [TK*512];
__device__ float g_kr [TK*512];
__device__ float g_vx [TK*HH];
__device__ float g_q  [TK*HH];   // [bh][s][64]
__device__ float g_k  [TK*HH];
__device__ float g_o  [TK*HH];
__device__ float g_h  [TK*HH];
__device__ float g_hn [TK*HH];
__device__ float g_gt [(NE+2)*TK*II];
__device__ float g_ut [(NE+2)*TK*II];
__device__ float g_act[(NE+2)*TK*II];
__device__ int   g_cnt[NE];
__device__ int   g_tok[NE*TK];
__device__ float g_twt[NE*TK];

// ---------------- mma helpers ----------------
__device__ __forceinline__ void mma16(float* c, const uint32_t* a, const uint32_t* b) {
    asm volatile(
        "mma.sync.aligned.m16n8k16.row.col.f32.bf16.bf16.f32 "
        "{%0,%1,%2,%3}, {%4,%5,%6,%7}, {%8,%9}, {%0,%1,%2,%3};\n"
        : "+f"(c[0]), "+f"(c[1]), "+f"(c[2]), "+f"(c[3])
        : "r"(a[0]), "r"(a[1]), "r"(a[2]), "r"(a[3]), "r"(b[0]), "r"(b[1]));
}
__device__ __forceinline__ uint32_t pkbf2(float a, float b) {
    __nv_bfloat162 t = __floats2bfloat162_rn(a, b);
    return *reinterpret_cast<uint32_t*>(&t);
}

// ---------------- unified bf16 GEMM ----------------
#define GASTR 20
#define GBSTR 136
#define GASZ  (128*GASTR)
#define GBSZ  (16*GBSTR)

struct GArgs {
    const float* A; int lda; size_t aes;
    const float* B[3]; int ldb[3]; size_t bes[3];
    float*       C[3]; int ldc[3]; size_t ces[3];
    int n1, n2;
    int M, N, K;
    const int* tok; int gatherA; int scatterC;
    const float* wt; const float* addsrc; int accAtomic;
    const int* cnt; int splitK;
};

__global__ void __launch_bounds__(256) gemm_bfx(GArgs ga)
{
    extern __shared__ uint32_t sm[];
    uint32_t* As = sm;
    uint32_t* Bs = sm + 2 * GASZ;
    __shared__ int idxs[128];

    int e, kbase, Ke;
    if (ga.splitK > 1) { e = 0; Ke = ga.K / ga.splitK; kbase = blockIdx.z * Ke; }
    else               { e = blockIdx.z; Ke = ga.K; kbase = 0; }

    const int m0 = blockIdx.y * 128;
    const int n0 = blockIdx.x * 128;

    int seg = 0, nloc = n0;
    if (ga.B[1] && n0 >= ga.n1) {
        if (ga.B[2] && n0 >= ga.n1 + ga.n2) { seg = 2; nloc = n0 - ga.n1 - ga.n2; }
        else                                { seg = 1; nloc = n0 - ga.n1; }
    }
    const float* A = ga.A + (size_t)e * ga.aes;
    const float* B = ga.B[seg] + (size_t)e * ga.bes[seg];
    float*       C = ga.C[seg] + (size_t)e * ga.ces[seg];
    const int lda = ga.lda, ldb = ga.ldb[seg], ldc = ga.ldc[seg];
    const int* idx = ga.tok ? ga.tok + (size_t)e * TK : nullptr;
    const float* wt = ga.wt ? ga.wt + (size_t)e * TK : nullptr;
    const int effM = ga.cnt ? ga.cnt[e] : ga.M;
    if (m0 >= effM) return;

    const int tid = threadIdx.x;
    if (idx) {
        for (int i = tid; i < 128; i += 256) {
            int m = m0 + i;
            idxs[i] = (m < effM) ? idx[m] : 0;
        }
        __syncthreads();
    }

    const int am = tid >> 4, ak2 = tid & 15;
    const int bn = tid & 127, bk2 = tid >> 7;

    float2 areg[8];
    float  breg[16];

    auto ldgTile = [&](int kt) {
        #pragma unroll
        for (int i = 0; i < 8; i++) {
            int m = am + i * 16;
            int mg = m0 + m;
            float2 v = make_float2(0.f, 0.f);
            if (mg < effM) {
                int row = ga.gatherA ? idxs[m] : mg;
                v = *(const float2*)(A + (size_t)row * lda + kt + 2 * ak2);
            }
            areg[i] = v;
        }
        #pragma unroll
        for (int i = 0; i < 8; i++) {
            int kk = kt + 2 * (bk2 + i * 2);
            breg[2 * i]     = B[(size_t)kk * ldb + nloc + bn];
            breg[2 * i + 1] = B[(size_t)(kk + 1) * ldb + nloc + bn];
        }
    };
    auto stsTile = [&](int buf) {
        uint32_t* Ad = As + buf * GASZ;
        #pragma unroll
        for (int i = 0; i < 8; i++)
            Ad[(am + i * 16) * GASTR + ak2] = pkbf2(areg[i].x, areg[i].y);
        uint32_t* Bd = Bs + buf * GBSZ;
        #pragma unroll
        for (int i = 0; i < 8; i++)
            Bd[(bk2 + i * 2) * GBSTR + bn] = pkbf2(breg[2 * i], breg[2 * i + 1]);
    };

    const int lane = tid & 31, wid = tid >> 5;
    const int wm = (wid >> 2) * 64;
    const int wn = (wid & 3) * 32;
    const int g = lane >> 2, c = lane & 3;

    float acc[4][4][4];
    #pragma unroll
    for (int i = 0; i < 4; i++)
        #pragma unroll
        for (int j = 0; j < 4; j++)
            #pragma unroll
            for (int r = 0; r < 4; r++) acc[i][j][r] = 0.f;

    ldgTile(kbase);
    stsTile(0);
    __syncthreads();

    const int nbuf = Ke >> 5;
    for (int t = 0; t < nbuf; t++) {
        int cur = t & 1;
        if (t + 1 < nbuf) ldgTile(kbase + ((t + 1) << 5));

        const uint32_t* Ab = As + cur * GASZ;
        const uint32_t* Bb = Bs + cur * GBSZ;
        #pragma unroll
        for (int kp = 0; kp < 16; kp += 8) {
            uint32_t af[4][4];
            #pragma unroll
            for (int mt = 0; mt < 4; mt++) {
                int mb = wm + mt * 16;
                af[mt][0] = Ab[(mb + g) * GASTR + kp + c];
                af[mt][1] = Ab[(mb + g + 8) * GASTR + kp + c];
                af[mt][2] = Ab[(mb + g) * GASTR + kp + c + 4];
                af[mt][3] = Ab[(mb + g + 8) * GASTR + kp + c + 4];
            }
            uint32_t bf[4][2];
            #pragma unroll
            for (int nt = 0; nt < 4; nt++) {
                int nb = wn + nt * 8;
                bf[nt][0] = Bb[(kp + c) * GBSTR + nb + g];
                bf[nt][1] = Bb[(kp + c + 4) * GBSTR + nb + g];
            }
            #pragma unroll
            for (int mt = 0; mt < 4; mt++)
                #pragma unroll
                for (int nt = 0; nt < 4; nt++)
                    mma16(acc[mt][nt], af[mt], bf[nt]);
        }
        if (t + 1 < nbuf) stsTile(cur ^ 1);
        __syncthreads();
    }

    #pragma unroll
    for (int mt = 0; mt < 4; mt++) {
        #pragma unroll
        for (int h2 = 0; h2 < 2; h2++) {
            int ml = wm + mt * 16 + g + h2 * 8;
            int m = m0 + ml;
            if (m >= effM) continue;
            int crow = ga.scatterC ? idxs[ml] : m;
            float sc = wt ? wt[m] : 1.f;
            #pragma unroll
            for (int nt = 0; nt < 4; nt++) {
                int ncol = nloc + wn + nt * 8 + c * 2;
                float v0 = acc[mt][nt][h2 * 2 + 0];
                float v1 = acc[mt][nt][h2 * 2 + 1];
                float* cp = C + (size_t)crow * ldc + ncol;
                if (ga.splitK > 1) {
                    atomicAdd(cp, v0); atomicAdd(cp + 1, v1);
                } else if (wt) {
                    atomicAdd(cp, sc * v0); atomicAdd(cp + 1, sc * v1);
                } else if (ga.accAtomic) {
                    atomicAdd(cp, v0); atomicAdd(cp + 1, v1);
                } else if (ga.addsrc) {
                    const float* ap = ga.addsrc + (size_t)m * ldc + ncol;
                    cp[0] = v0 + ap[0]; cp[1] = v1 + ap[1];
                } else {
                    cp[0] = v0; cp[1] = v1;
                }
            }
        }
    }
}

// ---------------- RMSNorm ----------------
__global__ void rms_k(const float* __restrict__ x, const float* __restrict__ w,
                      float* __restrict__ y, int D)
{
    int t = blockIdx.x;
    const float* xr = x + (size_t)t * D;
    float* yr = y + (size_t)t * D;
    float ss = 0.f;
    for (int k = threadIdx.x; k < D; k += blockDim.x) { float v = xr[k]; ss += v * v; }
    __shared__ float sh[32];
    int lane = threadIdx.x & 31, wid = threadIdx.x >> 5;
    #pragma unroll
    for (int o = 16; o > 0; o >>= 1) ss += __shfl_xor_sync(0xffffffffu, ss, o);
    if (lane == 0) sh[wid] = ss;
    __syncthreads();
    if (threadIdx.x == 0) {
        float tot = 0.f;
        int nw = blockDim.x >> 5;
        for (int i = 0; i < nw; i++) tot += sh[i];
        sh[0] = tot;
    }
    __syncthreads();
    float r = rsqrtf(sh[0] / (float)D + 1e-5f);
    for (int k = threadIdx.x; k < D; k += blockDim.x) yr[k] = w[k] * xr[k] * r;
}

// ---------------- fused: hn = rms(h), out = h, router top-2 ----------------
__global__ void __launch_bounds__(256) rms2_router_k(
    const float* __restrict__ h, const float* __restrict__ ln2w,
    const float* __restrict__ rw, const float* __restrict__ rb,
    float* __restrict__ hn, float* __restrict__ outp,
    int* __restrict__ cnt, int* __restrict__ tok, float* __restrict__ twt)
{
    int t = blockIdx.x;
    const int tid = threadIdx.x;
    const float* hr = h + (size_t)t * HH;
    float* hnr = hn + (size_t)t * HH;
    float* outr = outp + (size_t)t * HH;

    float hv[4];
    float ss = 0.f;
    #pragma unroll
    for (int i = 0; i < 4; i++) {
        int k = tid + i * 256;
        float v = hr[k];
        hv[i] = v;
        outr[k] = v;            // out = h (residual copy)
        ss += v * v;
    }
    __shared__ float sh[32];
    int lane = tid & 31, wid = tid >> 5;
    #pragma unroll
    for (int o = 16; o > 0; o >>= 1) ss += __shfl_xor_sync(0xffffffffu, ss, o);
    if (lane == 0) sh[wid] = ss;
    __syncthreads();
    if (tid == 0) {
        float tot = 0.f;
        for (int i = 0; i < 8; i++) tot += sh[i];
        sh[0] = tot;
    }
    __syncthreads();
    float r = rsqrtf(sh[0] / (float)HH + 1e-5f);

    float accv[NE];
    #pragma unroll
    for (int e = 0; e < NE; e++) accv[e] = 0.f;
    #pragma unroll
    for (int i = 0; i < 4; i++) {
        int k = tid + i * 256;
        float nv = ln2w[k] * hv[i] * r;
        hnr[k] = nv;
        const float* wrow = rw + (size_t)k * NE;
        #pragma unroll
        for (int e = 0; e < NE; e++) accv[e] += nv * wrow[e];
    }
    __shared__ float red[256][NE];
    #pragma unroll
    for (int e = 0; e < NE; e++) red[tid][e] = accv[e];
    __syncthreads();
    for (int s = 128; s > 0; s >>= 1) {
        if (tid < s)
            #pragma unroll
            for (int e = 0; e < NE; e++) red[tid][e] += red[tid + s][e];
        __syncthreads();
    }
    if (tid == 0) {
        float p[NE];
        #pragma unroll
        for (int e = 0; e < NE; e++) {
            float lg = red[0][e] + rb[e];
            p[e] = 1.f / (1.f + expf(-lg));
        }
        int e1 = 0;
        for (int e = 1; e < NE; e++) if (p[e] > p[e1]) e1 = e;
        int e2 = -1;
        for (int e = 0; e < NE; e++) if (e != e1 && (e2 < 0 || p[e] > p[e2])) e2 = e;
        float s2 = p[e1] + p[e2];
        float w1 = p[e1] / s2, w2 = p[e2] / s2;
        int a = atomicAdd(&cnt[e1], 1); tok[e1 * TK + a] = t; twt[e1 * TK + a] = w1;
        int b = atomicAdd(&cnt[e2], 1); tok[e2 * TK + b] = t; twt[e2 * TK + b] = w2;
    }
}

// ---------------- assemble Q/K with RoPE ----------------
__global__ void assemble_k(const float* __restrict__ qn, const float* __restrict__ qr,
                           const float* __restrict__ kn, const float* __restrict__ kr,
                           const float* __restrict__ cosp, const float* __restrict__ sinp,
                           float* __restrict__ Q, float* __restrict__ K)
{
    int idx = blockIdx.x * blockDim.x + threadIdx.x;
    if (idx >= BHN * SS * 64) return;
    int d  = idx & 63;
    int s  = (idx >> 6) & (SS - 1);
    int bh = idx >> 17;
    int b  = bh >> 4, h = bh & 15;
    int t  = b * SS + s;
    float qv, kv;
    if (d < 32) {
        qv = qn[(size_t)t * 512 + h * 32 + d];
        kv = kn[(size_t)t * 512 + h * 32 + d];
    } else {
        int j = d - 32;
        float cc = cosp[s * 32 + j];
        float sn = sinp[s * 32 + j];
        float q1 = qr[(size_t)t * 512 + h * 32 + j];
        float q2 = (j < 16) ? -qr[(size_t)t * 512 + h * 32 + j + 16]
                            :  qr[(size_t)t * 512 + h * 32 + j - 16];
        qv = q1 * cc + q2 * sn;
        float k1 = kr[(size_t)t * 512 + h * 32 + j];
        float k2 = (j < 16) ? -kr[(size_t)t * 512 + h * 32 + j + 16]
                            :  kr[(size_t)t * 512 + h * 32 + j - 16];
        kv = k1 * cc + k2 * sn;
    }
    Q[idx] = qv;
    K[idx] = kv;
}

// ---------------- flash attention, bf16, BM=128 ----------------
#define FQS 36
#define FKS 72
__global__ void __launch_bounds__(256) flash_bf(
    const float* __restrict__ Q, const float* __restrict__ Kg,
    const float* __restrict__ Vx, const float* __restrict__ maskp,
    float* __restrict__ O)
{
    extern __shared__ uint32_t sm[];
    uint32_t* Qs = sm;
    uint32_t* Kt = sm + 128 * FQS;
    uint32_t* Ps = Kt + 32 * FKS;
    uint32_t* Vs = Ps + 128 * FQS;

    const int bh = blockIdx.y;
    const int q0 = blockIdx.x * 128;
    const int b  = bh >> 4, hh = bh & 15;
    const float* Qb = Q  + (size_t)bh * SS * 64;
    const float* Kb = Kg + (size_t)bh * SS * 64;
    const float* Vb = Vx + (size_t)b * SS * HH + hh * 64;

    const int tid = threadIdx.x;
    const int w = tid >> 5, lane = tid & 31;
    const int g = lane >> 2, c = lane & 3;
    const int wrow = w * 16;

    const int qlr  = tid & 127;
    const int qlc0 = (tid >> 7) * 32;
    const int klr  = tid & 63;
    const int klc0 = (tid >> 6) * 16;
    const int vkp  = tid & 31;
    const int vdb  = (tid >> 5) * 8;

    {
        const float4* src = (const float4*)(Qb + (size_t)(q0 + qlr) * 64 + qlc0);
        #pragma unroll
        for (int i = 0; i < 8; i++) {
            float4 v = src[i];
            uint32_t* d = Qs + qlr * FQS + (qlc0 >> 1) + i * 2;
            d[0] = pkbf2(v.x, v.y);
            d[1] = pkbf2(v.z, v.w);
        }
    }

    float4 kreg[4];
    float4 vreg0[2], vreg1[2];
    auto ldgKV = [&](int k0) {
        const float4* ks = (const float4*)(Kb + (size_t)(k0 + klr) * 64 + klc0);
        #pragma unroll
        for (int i = 0; i < 4; i++) kreg[i] = ks[i];
        const float* v0p = Vb + (size_t)(k0 + 2 * vkp) * HH + vdb;
        const float* v1p = v0p + HH;
        #pragma unroll
        for (int i = 0; i < 2; i++) {
            vreg0[i] = *(const float4*)(v0p + i * 4);
            vreg1[i] = *(const float4*)(v1p + i * 4);
        }
    };
    auto stsKV = [&]() {
        #pragma unroll
        for (int i = 0; i < 4; i++) {
            float4 kv = kreg[i];
            int dp = (klc0 + i * 4) >> 1;
            Kt[(dp + 0) * FKS + klr] = pkbf2(kv.x, kv.y);
            Kt[(dp + 1) * FKS + klr] = pkbf2(kv.z, kv.w);
        }
        #pragma unroll
        for (int i = 0; i < 2; i++) {
            float4 a = vreg0[i];
            float4 bb = vreg1[i];
            uint32_t* vd = Vs + vkp * FKS + vdb + i * 4;
            vd[0] = pkbf2(a.x, bb.x);
            vd[1] = pkbf2(a.y, bb.y);
            vd[2] = pkbf2(a.z, bb.z);
            vd[3] = pkbf2(a.w, bb.w);
        }
    };

    float oacc[8][4];
    #pragma unroll
    for (int nf = 0; nf < 8; nf++)
        #pragma unroll
        for (int r = 0; r < 4; r++) oacc[nf][r] = 0.f;
    float m0 = -1e30f, m1 = -1e30f, l0 = 0.f, l1 = 0.f;

    const float* mr0 = maskp + (size_t)(q0 + wrow + g) * SS;
    const float* mr1 = mr0 + 8 * SS;

    ldgKV(0);
    for (int k0 = 0; k0 < SS; k0 += 64) {
        __syncthreads();
        stsKV();
        __syncthreads();
        if (k0 + 64 < SS) ldgKV(k0 + 64);

        float sacc[8][4];
        #pragma unroll
        for (int nf = 0; nf < 8; nf++)
            #pragma unroll
            for (int r = 0; r < 4; r++) sacc[nf][r] = 0.f;
        #pragma unroll
        for (int ks = 0; ks < 32; ks += 8) {
            uint32_t af[4];
            af[0] = Qs[(wrow + g) * FQS + ks + c];
            af[1] = Qs[(wrow + g + 8) * FQS + ks + c];
            af[2] = Qs[(wrow + g) * FQS + ks + c + 4];
            af[3] = Qs[(wrow + g + 8) * FQS + ks + c + 4];
            #pragma unroll
            for (int nf = 0; nf < 8; nf++) {
                uint32_t bf[2];
                bf[0] = Kt[(ks + c) * FKS + nf * 8 + g];
                bf[1] = Kt[(ks + c + 4) * FKS + nf * 8 + g];
                mma16(sacc[nf], af, bf);
            }
        }

        float mx0 = -1e30f, mx1 = -1e30f;
        #pragma unroll
        for (int nf = 0; nf < 8; nf++) {
            float2 mk0 = *(const float2*)(mr0 + k0 + nf * 8 + 2 * c);
            float2 mk1 = *(const float2*)(mr1 + k0 + nf * 8 + 2 * c);
            sacc[nf][0] = sacc[nf][0] * 0.125f + mk0.x;
            sacc[nf][1] = sacc[nf][1] * 0.125f + mk0.y;
            sacc[nf][2] = sacc[nf][2] * 0.125f + mk1.x;
            sacc[nf][3] = sacc[nf][3] * 0.125f + mk1.y;
            mx0 = fmaxf(mx0, fmaxf(sacc[nf][0], sacc[nf][1]));
            mx1 = fmaxf(mx1, fmaxf(sacc[nf][2], sacc[nf][3]));
        }
        mx0 = fmaxf(mx0, __shfl_xor_sync(0xffffffffu, mx0, 1));
        mx0 = fmaxf(mx0, __shfl_xor_sync(0xffffffffu, mx0, 2));
        mx1 = fmaxf(mx1, __shfl_xor_sync(0xffffffffu, mx1, 1));
        mx1 = fmaxf(mx1, __shfl_xor_sync(0xffffffffu, mx1, 2));

        float mn0 = fmaxf(m0, mx0), mn1 = fmaxf(m1, mx1);
        float cr0 = __expf(m0 - mn0), cr1 = __expf(m1 - mn1);
        m0 = mn0; m1 = mn1;
        float rs0 = 0.f, rs1 = 0.f;
        #pragma unroll
        for (int nf = 0; nf < 8; nf++) {
            sacc[nf][0] = __expf(sacc[nf][0] - mn0);
            sacc[nf][1] = __expf(sacc[nf][1] - mn0);
            sacc[nf][2] = __expf(sacc[nf][2] - mn1);
            sacc[nf][3] = __expf(sacc[nf][3] - mn1);
            rs0 += sacc[nf][0] + sacc[nf][1];
            rs1 += sacc[nf][2] + sacc[nf][3];
        }
        rs0 += __shfl_xor_sync(0xffffffffu, rs0, 1);
        rs0 += __shfl_xor_sync(0xffffffffu, rs0, 2);
        rs1 += __shfl_xor_sync(0xffffffffu, rs1, 1);
        rs1 += __shfl_xor_sync(0xffffffffu, rs1, 2);
        l0 = l0 * cr0 + rs0;
        l1 = l1 * cr1 + rs1;
        #pragma unroll
        for (int nf = 0; nf < 8; nf++) {
            oacc[nf][0] *= cr0; oacc[nf][1] *= cr0;
            oacc[nf][2] *= cr1; oacc[nf][3] *= cr1;
        }

        #pragma unroll
        for (int nf = 0; nf < 8; nf++) {
            int kp = nf * 4 + c;
            Ps[(wrow + g) * FQS + kp]     = pkbf2(sacc[nf][0], sacc[nf][1]);
            Ps[(wrow + g + 8) * FQS + kp] = pkbf2(sacc[nf][2], sacc[nf][3]);
        }
        __syncwarp();

        #pragma unroll
        for (int kk = 0; kk < 32; kk += 8) {
            uint32_t af[4];
            af[0] = Ps[(wrow + g) * FQS + kk + c];
            af[1] = Ps[(wrow + g + 8) * FQS + kk + c];
            af[2] = Ps[(wrow + g) * FQS + kk + c + 4];
            af[3] = Ps[(wrow + g + 8) * FQS + kk + c + 4];
            #pragma unroll
            for (int nf = 0; nf < 8; nf++) {
                uint32_t bf[2];
                bf[0] = Vs[(kk + c) * FKS + nf * 8 + g];
                bf[1] = Vs[(kk + c + 4) * FKS + nf * 8 + g];
                mma16(oacc[nf], af, bf);
            }
        }
    }

    float inv0 = 1.f / l0, inv1 = 1.f / l1;
    int row0 = q0 + wrow + g;
    float* o0 = O + ((size_t)(b * SS + row0)) * HH + hh * 64;
    float* o1 = o0 + 8 * (size_t)HH;
    #pragma unroll
    for (int nf = 0; nf < 8; nf++) {
        int col = nf * 8 + 2 * c;
        float2 v0 = make_float2(oacc[nf][0] * inv0, oacc[nf][1] * inv0);
        float2 v1 = make_float2(oacc[nf][2] * inv1, oacc[nf][3] * inv1);
        *(float2*)(o0 + col) = v0;
        *(float2*)(o1 + col) = v1;
    }
}

// ---------------- silu kernels (A2 fusion reverted: silu computed ONCE per element) ----------------
__global__ void silu_mul_k(const float* __restrict__ g, const float* __restrict__ u,
                           float* __restrict__ y, int n)
{
    int i = blockIdx.x * 256 + threadIdx.x;
    if (i < n) {
        float gv = g[i];
        y[i] = (gv / (1.f + __expf(-gv))) * u[i];
    }
}

__global__ void silu_mul_moe(const float* __restrict__ g, const float* __restrict__ u,
                             float* __restrict__ y, const int* __restrict__ cnt)
{
    const size_t TI = (size_t)TK * II;
    int e = blockIdx.y;
    int i = blockIdx.x * 256 + threadIdx.x;
    if (i / II >= cnt[e]) return;
    size_t idx = (size_t)e * TI + i;
    float gv = g[idx];
    y[idx] = (gv / (1.f + __expf(-gv))) * u[idx];
}

__global__ void usage_k(const int* __restrict__ cnt, float* __restrict__ out)
{
    int e = threadIdx.x;
    if (e < NE) out[e] = (float)cnt[e];
}

// ---------------- host-side dispatch ----------------
static const int SMEMB = (2 * (GASZ + GBSZ)) * 4;   // 37888
static const int SMEMF = (128 * FQS + 32 * FKS + 128 * FQS + 32 * FKS) * 4;  // 55296

static GArgs mkargs(const float* A, int lda, size_t aes,
                    const float* B0, int ldb0, size_t bes0,
                    float* C0, int ldc0, size_t ces0,
                    int M, int N, int K)
{
    GArgs ga = {};
    ga.A = A; ga.lda = lda; ga.aes = aes;
    ga.B[0] = B0; ga.ldb[0] = ldb0; ga.bes[0] = bes0;
    ga.C[0] = C0; ga.ldc[0] = ldc0; ga.ces[0] = ces0;
    ga.n1 = N; ga.n2 = 0;
    ga.M = M; ga.N = N; ga.K = K;
    ga.splitK = 1;
    return ga;
}

static void launch(cudaStream_t st, const GArgs& ga, int nz)
{
    dim3 grid(ga.N / 128, (ga.M + 127) / 128, nz);
    gemm_bfx<<<grid, 256, SMEMB, st>>>(ga);
}

extern "C" void kernel_launch(void* const* d_in, const int* in_sizes, int n_in,
                              void* d_out, int out_size)
{
    const float* x        = (const float*)d_in[0];
    const float* cosp     = (const float*)d_in[1];
    const float* sinp     = (const float*)d_in[2];
    const float* maskp    = (const float*)d_in[3];
    const float* ln1      = (const float*)d_in[4];
    const float* ln2      = (const float*)d_in[5];
    const float* kv_down  = (const float*)d_in[6];
    const float* kv_norm  = (const float*)d_in[7];
    const float* w_uk     = (const float*)d_in[8];
    const float* w_ur     = (const float*)d_in[9];
    const float* w_uv     = (const float*)d_in[10];
    const float* q_down   = (const float*)d_in[11];
    const float* q_norm   = (const float*)d_in[12];
    const float* w_uq     = (const float*)d_in[13];
    const float* w_qr     = (const float*)d_in[14];
    const float* o_proj   = (const float*)d_in[15];
    const float* sh_gate  = (const float*)d_in[16];
    const float* sh_up    = (const float*)d_in[17];
    const float* sh_down  = (const float*)d_in[18];
    const float* r_gate   = (const float*)d_in[19];
    const float* r_up     = (const float*)d_in[20];
    const float* r_down   = (const float*)d_in[21];
    const float* router_w = (const float*)d_in[22];
    const float* router_b = (const float*)d_in[23];
    float* out = (float*)d_out;

    float *xi, *cq, *ckv, *qn, *qr, *kn, *kr, *vx, *q, *k, *o, *h, *hn, *gt, *ut, *act, *twt;
    int *cnt, *tok;
    cudaGetSymbolAddress((void**)&xi,  g_xi);
    cudaGetSymbolAddress((void**)&cq,  g_cq);
    cudaGetSymbolAddress((void**)&ckv, g_ckv);
    cudaGetSymbolAddress((void**)&qn,  g_qn);
    cudaGetSymbolAddress((void**)&qr,  g_qr);
    cudaGetSymbolAddress((void**)&kn,  g_kn);
    cudaGetSymbolAddress((void**)&kr,  g_kr);
    cudaGetSymbolAddress((void**)&vx,  g_vx);
    cudaGetSymbolAddress((void**)&q,   g_q);
    cudaGetSymbolAddress((void**)&k,   g_k);
    cudaGetSymbolAddress((void**)&o,   g_o);
    cudaGetSymbolAddress((void**)&h,   g_h);
    cudaGetSymbolAddress((void**)&hn,  g_hn);
    cudaGetSymbolAddress((void**)&gt,  g_gt);
    cudaGetSymbolAddress((void**)&ut,  g_ut);
    cudaGetSymbolAddress((void**)&act, g_act);
    cudaGetSymbolAddress((void**)&twt, g_twt);
    cudaGetSymbolAddress((void**)&cnt, g_cnt);
    cudaGetSymbolAddress((void**)&tok, g_tok);

    cudaFuncSetAttribute(gemm_bfx, cudaFuncAttributeMaxDynamicSharedMemorySize, SMEMB);
    cudaFuncSetAttribute(flash_bf, cudaFuncAttributeMaxDynamicSharedMemorySize, SMEMF);

    cudaStream_t s0 = 0, s1;
    cudaStreamCreateWithFlags(&s1, cudaStreamNonBlocking);
    cudaEvent_t ev0, ev1, ev2, ev3;
    cudaEventCreateWithFlags(&ev0, cudaEventDisableTiming);
    cudaEventCreateWithFlags(&ev1, cudaEventDisableTiming);
    cudaEventCreateWithFlags(&ev2, cudaEventDisableTiming);
    cudaEventCreateWithFlags(&ev3, cudaEventDisableTiming);

    const size_t TI = (size_t)TK * II;
    const size_t WE = (size_t)HH * II;
    const size_t WD = (size_t)II * HH;

    // ---- MLA attention ----
    rms_k<<<TK, 256, 0, s0>>>(x, ln1, xi, HH);

    cudaMemsetAsync(cq, 0, (size_t)TK * 128 * sizeof(float), s0);
    cudaMemsetAsync(ckv, 0, (size_t)TK * 128 * sizeof(float), s0);
    {
        GArgs ga = mkargs(xi, HH, 0, q_down, 128, 0, cq, 128, 0, TK, 256, HH);
        ga.n1 = 128;
        ga.B[1] = kv_down; ga.ldb[1] = 128; ga.bes[1] = 0;
        ga.C[1] = ckv;     ga.ldc[1] = 128; ga.ces[1] = 0;
        ga.splitK = 4;
        launch(s0, ga, 4);
    }
    rms_k<<<TK, 128, 0, s0>>>(cq, q_norm, cq, 128);
    cudaEventRecord(ev0, s0);
    cudaStreamWaitEvent(s1, ev0, 0);
    rms_k<<<TK, 128, 0, s1>>>(ckv, kv_norm, ckv, 128);

    {
        GArgs ga = mkargs(cq, 128, 0, w_uq, 512, 0, qn, 512, 0, TK, 1024, 128);
        ga.n1 = 512;
        ga.B[1] = w_qr; ga.ldb[1] = 512; ga.bes[1] = 0;
        ga.C[1] = qr;   ga.ldc[1] = 512; ga.ces[1] = 0;
        launch(s0, ga, 1);
    }
    {
        GArgs ga = mkargs(ckv, 128, 0, w_uk, 512, 0, kn, 512, 0, TK, 2048, 128);
        ga.n1 = 512; ga.n2 = 512;
        ga.B[1] = w_ur; ga.ldb[1] = 512;  ga.bes[1] = 0;
        ga.C[1] = kr;   ga.ldc[1] = 512;  ga.ces[1] = 0;
        ga.B[2] = w_uv; ga.ldb[2] = 1024; ga.bes[2] = 0;
        ga.C[2] = vx;   ga.ldc[2] = 1024; ga.ces[2] = 0;
        launch(s1, ga, 1);
    }
    cudaEventRecord(ev1, s1);
    cudaStreamWaitEvent(s0, ev1, 0);

    assemble_k<<<(BHN * SS * 64) / 256, 256, 0, s0>>>(qn, qr, kn, kr, cosp, sinp, q, k);
    flash_bf<<<dim3(SS / 128, BHN), 256, SMEMF, s0>>>(q, k, vx, maskp, o);
    {
        GArgs ga = mkargs(o, HH, 0, o_proj, HH, 0, h, HH, 0, TK, HH, HH);
        ga.addsrc = x;
        launch(s0, ga, 1);
    }

    // ---- MoE (bf16; fused rms+residual-copy+router; separate silu passes) ----
    cudaMemsetAsync(cnt, 0, NE * sizeof(int), s0);
    rms2_router_k<<<TK, 256, 0, s0>>>(h, ln2, router_w, router_b, hn, out, cnt, tok, twt);
    cudaEventRecord(ev2, s0);
    cudaStreamWaitEvent(s1, ev2, 0);

    // shared experts on s0 (z=2): merged gate|up, silu, down (atomic acc)
    {
        GArgs ga = mkargs(hn, HH, 0, sh_gate, II, WE, gt, II, TI, TK, 768, HH);
        ga.n1 = II;
        ga.B[1] = sh_up; ga.ldb[1] = II; ga.bes[1] = WE;
        ga.C[1] = ut;    ga.ldc[1] = II; ga.ces[1] = TI;
        launch(s0, ga, 2);
    }
    silu_mul_k<<<(2 * (int)TI + 255) / 256, 256, 0, s0>>>(gt, ut, act, 2 * (int)TI);
    {
        GArgs ga = mkargs(act, II, TI, sh_down, HH, WD, out, HH, 0, TK, HH, II);
        ga.accAtomic = 1;
        launch(s0, ga, 2);
    }

    // routed experts on s1 (z=8, gather): merged gate|up, silu, down (scatter+scale)
    float* gt2 = gt + 2 * TI;
    float* ut2 = ut + 2 * TI;
    float* act2 = act + 2 * TI;
    {
        GArgs ga = mkargs(hn, HH, 0, r_gate, II, WE, gt2, II, TI, TK, 768, HH);
        ga.n1 = II;
        ga.B[1] = r_up; ga.ldb[1] = II; ga.bes[1] = WE;
        ga.C[1] = ut2;  ga.ldc[1] = II; ga.ces[1] = TI;
        ga.tok = tok; ga.gatherA = 1; ga.cnt = cnt;
        launch(s1, ga, NE);
    }
    silu_mul_moe<<<dim3(((int)TI + 255) / 256, NE), 256, 0, s1>>>(gt2, ut2, act2, cnt);
    {
        GArgs ga = mkargs(act2, II, TI, r_down, HH, WD, out, HH, 0, TK, HH, II);
        ga.tok = tok; ga.scatterC = 1; ga.wt = twt; ga.cnt = cnt;
        launch(s1, ga, NE);
    }
    cudaEventRecord(ev3, s1);
    cudaStreamWaitEvent(s0, ev3, 0);

    usage_k<<<1, NE, 0, s0>>>(cnt, out + (size_t)TK * HH);
}